// round 2
// baseline (speedup 1.0000x reference)
#include <cuda_runtime.h>
#include <math.h>
#include <stdint.h>

// ---------------- scratch ----------------
__device__ float g_h1[67108864];   // [32,128,128,128]
__device__ float g_h2[8388608];    // [32,64,64,64]
__device__ float g_z [8388608];    // NHWC [32,64,64][64]
__device__ float g_q [8388608];    // NCHW [32,64,64,64]
__device__ float g_g1[67108864];   // [32,128,128,128]
__device__ float g_g2[134217728];  // [32,64,256,256]
__device__ int    g_idx[131072];
__device__ float  g_ee[512];
__device__ float  g_counts[512];
__device__ double g_loss_sum;

__global__ void k_init() {
    int t = threadIdx.x;
    if (t < 512) g_counts[t] = 0.f;
    if (t == 0) g_loss_sum = 0.0;
}

// conv1: x[32,1,256,256] -> h1[32,128,128,128], 4x4 s2 p1, relu
__global__ void __launch_bounds__(128) k_conv1(const float* __restrict__ x,
                                               const float* __restrict__ w,
                                               const float* __restrict__ b) {
    __shared__ float sW[2048];
    __shared__ float sB[128];
    int ox = threadIdx.x, oy = blockIdx.x, n = blockIdx.y;
    for (int i = threadIdx.x; i < 2048; i += 128) sW[i] = w[i];
    sB[threadIdx.x] = b[threadIdx.x];
    __syncthreads();
    float p[16];
    const float* xb = x + (size_t)n * 65536;
#pragma unroll
    for (int ky = 0; ky < 4; ky++) {
        int iy = oy * 2 - 1 + ky;
#pragma unroll
        for (int kx = 0; kx < 4; kx++) {
            int ix = ox * 2 - 1 + kx;
            p[ky * 4 + kx] = (iy >= 0 && iy < 256 && ix >= 0 && ix < 256) ? xb[iy * 256 + ix] : 0.f;
        }
    }
    float* ob = g_h1 + (size_t)n * 2097152 + (size_t)oy * 128 + ox;
    for (int c = 0; c < 128; c++) {
        const float4* wp = (const float4*)&sW[c * 16];
        float a = sB[c];
#pragma unroll
        for (int u = 0; u < 4; u++) {
            float4 t4 = wp[u];
            a += t4.x * p[4*u] + t4.y * p[4*u+1] + t4.z * p[4*u+2] + t4.w * p[4*u+3];
        }
        ob[(size_t)c * 16384] = fmaxf(a, 0.f);
    }
}

// conv2: h1 -> h2[32,64,64,64], 128ic 4x4 s2 p1, relu. tile 32x*8y*64oc
__global__ void __launch_bounds__(256) k_conv2(const float* __restrict__ w,
                                               const float* __restrict__ b) {
    __shared__ float sIn[4 * 18 * 66];
    __shared__ float sW[4096];
    int tid = threadIdx.x;
    int tx = tid & 7, ty = (tid >> 3) & 7, tz = tid >> 6;
    int n = blockIdx.z, oy0 = blockIdx.y * 8, ox0 = blockIdx.x * 32;
    const float* inb = g_h1 + (size_t)n * 2097152;
    float acc[4][16] = {};
    const int IY0 = oy0 * 2 - 1, IX0 = ox0 * 2 - 1;
    for (int ic0 = 0; ic0 < 128; ic0 += 4) {
        __syncthreads();
        for (int i = tid; i < 4 * 18 * 66; i += 256) {
            int j = i / 1188, rem = i - j * 1188, yy = rem / 66, xx = rem - yy * 66;
            int iy = IY0 + yy, ix = IX0 + xx;
            float v = 0.f;
            if (iy >= 0 && iy < 128 && ix >= 0 && ix < 128)
                v = inb[((size_t)(ic0 + j) * 128 + iy) * 128 + ix];
            sIn[i] = v;
        }
        for (int i = tid; i < 4096; i += 256) {
            int j = i >> 10, rem = i & 1023, t = rem >> 6, oc = rem & 63;
            sW[i] = w[((size_t)(oc << 7) + ic0 + j) * 16 + t];
        }
        __syncthreads();
#pragma unroll
        for (int j = 0; j < 4; j++) {
#pragma unroll
            for (int ky = 0; ky < 4; ky++) {
                const float* rp = &sIn[(j * 18 + ty * 2 + ky) * 66 + tx * 8];
#pragma unroll
                for (int kx = 0; kx < 4; kx++) {
                    float v0 = rp[kx], v1 = rp[kx+2], v2 = rp[kx+4], v3 = rp[kx+6];
                    const float4* wp = (const float4*)&sW[((j << 4) + (ky << 2) + kx) * 64 + tz * 16];
                    float wv[16];
#pragma unroll
                    for (int u = 0; u < 4; u++) {
                        float4 t4 = wp[u];
                        wv[4*u]=t4.x; wv[4*u+1]=t4.y; wv[4*u+2]=t4.z; wv[4*u+3]=t4.w;
                    }
#pragma unroll
                    for (int o = 0; o < 16; o++) {
                        acc[0][o] += v0 * wv[o];
                        acc[1][o] += v1 * wv[o];
                        acc[2][o] += v2 * wv[o];
                        acc[3][o] += v3 * wv[o];
                    }
                }
            }
        }
    }
    int oy = oy0 + ty;
#pragma unroll
    for (int o = 0; o < 16; o++) {
        int oc = tz * 16 + o;
        float bb = b[oc];
        float4 r;
        r.x = fmaxf(acc[0][o] + bb, 0.f);
        r.y = fmaxf(acc[1][o] + bb, 0.f);
        r.z = fmaxf(acc[2][o] + bb, 0.f);
        r.w = fmaxf(acc[3][o] + bb, 0.f);
        *(float4*)&g_h2[(((size_t)n * 64 + oc) * 64 + oy) * 64 + ox0 + tx * 4] = r;
    }
}

// conv3: h2 -> z NHWC, 64ic 3x3 s1 p1
__global__ void __launch_bounds__(256) k_conv3(const float* __restrict__ w,
                                               const float* __restrict__ b) {
    __shared__ float sIn[8 * 10 * 34];
    __shared__ float sW[8 * 9 * 64];
    int tid = threadIdx.x;
    int tx = tid & 7, ty = (tid >> 3) & 7, tz = tid >> 6;
    int n = blockIdx.z, oy0 = blockIdx.y * 8, ox0 = blockIdx.x * 32;
    const float* inb = g_h2 + (size_t)n * 262144;
    float acc[4][16] = {};
    for (int ic0 = 0; ic0 < 64; ic0 += 8) {
        __syncthreads();
        for (int i = tid; i < 8 * 10 * 34; i += 256) {
            int j = i / 340, rem = i - j * 340, yy = rem / 34, xx = rem - yy * 34;
            int iy = oy0 - 1 + yy, ix = ox0 - 1 + xx;
            float v = 0.f;
            if (iy >= 0 && iy < 64 && ix >= 0 && ix < 64)
                v = inb[((size_t)(ic0 + j) * 64 + iy) * 64 + ix];
            sIn[i] = v;
        }
        for (int i = tid; i < 8 * 9 * 64; i += 256) {
            int j = i / 576, rem = i - j * 576, t = rem >> 6, oc = rem & 63;
            sW[i] = w[((size_t)oc * 64 + ic0 + j) * 9 + t];
        }
        __syncthreads();
#pragma unroll
        for (int j = 0; j < 8; j++) {
#pragma unroll
            for (int ky = 0; ky < 3; ky++) {
                const float* rp = &sIn[(j * 10 + ty + ky) * 34 + tx * 4];
                float v[6];
#pragma unroll
                for (int c = 0; c < 6; c++) v[c] = rp[c];
#pragma unroll
                for (int kx = 0; kx < 3; kx++) {
                    const float4* wp = (const float4*)&sW[(j * 9 + ky * 3 + kx) * 64 + tz * 16];
                    float wv[16];
#pragma unroll
                    for (int u = 0; u < 4; u++) {
                        float4 t4 = wp[u];
                        wv[4*u]=t4.x; wv[4*u+1]=t4.y; wv[4*u+2]=t4.z; wv[4*u+3]=t4.w;
                    }
#pragma unroll
                    for (int q = 0; q < 4; q++)
#pragma unroll
                        for (int o = 0; o < 16; o++) acc[q][o] += v[q + kx] * wv[o];
                }
            }
        }
    }
    int oy = oy0 + ty;
#pragma unroll
    for (int q = 0; q < 4; q++) {
        int ox = ox0 + tx * 4 + q;
        float* zp = g_z + (((size_t)n * 64 + oy) * 64 + ox) * 64 + tz * 16;
#pragma unroll
        for (int g = 0; g < 4; g++) {
            float4 r;
            r.x = acc[q][4*g+0] + b[tz*16 + 4*g+0];
            r.y = acc[q][4*g+1] + b[tz*16 + 4*g+1];
            r.z = acc[q][4*g+2] + b[tz*16 + 4*g+2];
            r.w = acc[q][4*g+3] + b[tz*16 + 4*g+3];
            ((float4*)zp)[g] = r;
        }
    }
}

__global__ void k_ee(const float* __restrict__ emb) {
    int k = threadIdx.x;
    float s = 0.f;
    for (int d = 0; d < 64; d++) { float e = emb[d * 512 + k]; s += e * e; }
    g_ee[k] = s;
}

// VQ argmin
__global__ void __launch_bounds__(256) k_vq(const float* __restrict__ emb) {
    __shared__ float sE[64 * 68];
    __shared__ float sEE[64];
    int tid = threadIdx.x;
    int row = blockIdx.x * 256 + tid;
    float zr[64];
    const float4* zp = (const float4*)(g_z + (size_t)row * 64);
#pragma unroll
    for (int j = 0; j < 16; j++) {
        float4 t = zp[j];
        zr[4*j]=t.x; zr[4*j+1]=t.y; zr[4*j+2]=t.z; zr[4*j+3]=t.w;
    }
    float best = 3.4e38f;
    int bi = 0;
    for (int kc = 0; kc < 512; kc += 64) {
        __syncthreads();
        for (int i = tid; i < 4096; i += 256) {
            int d = i >> 6, k = i & 63;
            sE[k * 68 + d] = emb[d * 512 + kc + k];
        }
        if (tid < 64) sEE[tid] = g_ee[kc + tid];
        __syncthreads();
        for (int k = 0; k < 64; k++) {
            const float4* ep = (const float4*)&sE[k * 68];
            float s0=0.f, s1=0.f, s2=0.f, s3=0.f;
#pragma unroll
            for (int j = 0; j < 16; j++) {
                float4 e = ep[j];
                s0 += zr[4*j] * e.x; s1 += zr[4*j+1] * e.y;
                s2 += zr[4*j+2] * e.z; s3 += zr[4*j+3] * e.w;
            }
            float dd = sEE[k] - 2.f * ((s0 + s1) + (s2 + s3));
            if (dd < best) { best = dd; bi = kc + k; }
        }
    }
    g_idx[row] = bi;
    atomicAdd(&g_counts[bi], 1.f);
}

// gather codes + loss + NCHW transpose (128 rows/block)
__global__ void __launch_bounds__(256) k_gather(const float* __restrict__ emb) {
    __shared__ float sQ[8192];
    __shared__ float sRed[256];
    int tid = threadIdx.x;
    int r0 = blockIdx.x * 128;
    int rl = tid & 127, half = tid >> 7;
    int r = r0 + rl;
    int id = g_idx[r];
    const float4* z4 = (const float4*)(g_z + (size_t)r * 64 + half * 32);
    float ls = 0.f;
#pragma unroll
    for (int jj = 0; jj < 8; jj++) {
        float4 zv = z4[jj];
        int d = half * 32 + jj * 4;
        float e0 = emb[(d+0)*512 + id];
        float e1 = emb[(d+1)*512 + id];
        float e2 = emb[(d+2)*512 + id];
        float e3 = emb[(d+3)*512 + id];
        float d0=e0-zv.x, d1=e1-zv.y, d2=e2-zv.z, d3=e3-zv.w;
        ls += d0*d0 + d1*d1 + d2*d2 + d3*d3;
        sQ[(d+0)*128 + rl] = e0;
        sQ[(d+1)*128 + rl] = e1;
        sQ[(d+2)*128 + rl] = e2;
        sQ[(d+3)*128 + rl] = e3;
    }
    __syncthreads();
    int n = r0 >> 12;
    int y0x = r0 & 4095;
    float* qb = g_q + ((size_t)n << 18) + y0x;
    for (int i = tid; i < 8192; i += 256) {
        int d = i >> 7, rl2 = i & 127;
        qb[(size_t)d * 4096 + rl2] = sQ[i];
    }
    sRed[tid] = ls;
    __syncthreads();
    for (int s = 128; s > 0; s >>= 1) {
        if (tid < s) sRed[tid] += sRed[tid + s];
        __syncthreads();
    }
    if (tid == 0) atomicAdd(&g_loss_sum, (double)sRed[0]);
}

__global__ void k_finalize(float* __restrict__ out, int out_size) {
    __shared__ float red[512];
    int t = threadIdx.x;
    float c = g_counts[t];
    float p = c * (1.f / 131072.f);
    red[t] = p * logf(p + 1e-10f);
    __syncthreads();
    for (int s = 256; s > 0; s >>= 1) {
        if (t < s) red[t] += red[t + s];
        __syncthreads();
    }
    if (t == 0) {
        out[out_size - 1] = expf(-red[0]);
        out[0] = (float)(g_loss_sum * (1.25 / 8388608.0));
    }
}

// transposed conv 3x3 s2 p1 op1, relu. out[oy]=sum in[iy]*w[oy-2iy+1]
__global__ void __launch_bounds__(256) k_convT(const float* __restrict__ in,
                                               const float* __restrict__ w,
                                               const float* __restrict__ b,
                                               float* __restrict__ out,
                                               int IC, int OC, int INS, int OUTS) {
    __shared__ float sIn[8 * 17 * 33];
    __shared__ float sW[576];
    int tid = threadIdx.x;
    int tx = tid & 15, ty = tid >> 4;
    int ocChunks = OC >> 3;
    int z = blockIdx.z;
    int oc0 = (z % ocChunks) * 8;
    int n = z / ocChunks;
    int ux0 = blockIdx.x * 32, uy0 = blockIdx.y * 16;
    const float* inb = in + (size_t)n * IC * INS * INS;
    float acc[2][4][8] = {};
    for (int ic0 = 0; ic0 < IC; ic0 += 8) {
        __syncthreads();
        for (int i = tid; i < 8 * 17 * 33; i += 256) {
            int j = i / 561, rem = i - j * 561, yy = rem / 33, xx = rem - yy * 33;
            int iy = uy0 + yy, ix = ux0 + xx;
            sIn[i] = (iy < INS && ix < INS) ? inb[((size_t)(ic0 + j) * INS + iy) * INS + ix] : 0.f;
        }
        for (int i = tid; i < 576; i += 256) {
            int j = i / 72, rem = i - j * 72, tap = rem >> 3, o = rem & 7;
            sW[i] = w[((size_t)(ic0 + j) * OC + oc0 + o) * 9 + tap];
        }
        __syncthreads();
#pragma unroll
        for (int j = 0; j < 8; j++) {
            float v[2][3];
#pragma unroll
            for (int rr = 0; rr < 2; rr++)
#pragma unroll
                for (int cc = 0; cc < 3; cc++)
                    v[rr][cc] = sIn[(j * 17 + ty + rr) * 33 + 2 * tx + cc];
#pragma unroll
            for (int ky = 0; ky < 3; ky++) {
                int vr = (ky == 0) ? 1 : 0;
                int dy = (ky == 1) ? 0 : 1;
#pragma unroll
                for (int kx = 0; kx < 3; kx++) {
                    const float4* wp = (const float4*)&sW[(j * 9 + ky * 3 + kx) * 8];
                    float4 w0 = wp[0], w1 = wp[1];
                    float wv[8] = {w0.x,w0.y,w0.z,w0.w,w1.x,w1.y,w1.z,w1.w};
                    int c0, dA, c1, dB;
                    if (kx == 0)      { c0 = 1; dA = 1; c1 = 2; dB = 3; }
                    else if (kx == 1) { c0 = 0; dA = 0; c1 = 1; dB = 2; }
                    else              { c0 = 0; dA = 1; c1 = 1; dB = 3; }
                    float va = v[vr][c0], vb = v[vr][c1];
#pragma unroll
                    for (int o = 0; o < 8; o++) {
                        acc[dy][dA][o] += va * wv[o];
                        acc[dy][dB][o] += vb * wv[o];
                    }
                }
            }
        }
    }
    int uy = uy0 + ty;
    int oxb = 2 * ux0 + 4 * tx;
#pragma unroll
    for (int o = 0; o < 8; o++) {
        float bb = b[oc0 + o];
#pragma unroll
        for (int dy = 0; dy < 2; dy++) {
            int oy = 2 * uy + dy;
            float4 r;
            r.x = fmaxf(acc[dy][0][o] + bb, 0.f);
            r.y = fmaxf(acc[dy][1][o] + bb, 0.f);
            r.z = fmaxf(acc[dy][2][o] + bb, 0.f);
            r.w = fmaxf(acc[dy][3][o] + bb, 0.f);
            *(float4*)&out[(((size_t)n * OC + oc0 + o) * OUTS + oy) * OUTS + oxb] = r;
        }
    }
}

// convT3: g2 -> recon[32,1,256,256]: conv with flipped kernel, pad1
__global__ void __launch_bounds__(256) k_convT3(const float* __restrict__ w,
                                                const float* __restrict__ b,
                                                float* __restrict__ out) {
    __shared__ float sIn[8 * 18 * 66];
    __shared__ float sW[576];
    int tid = threadIdx.x;
    int tx = tid & 15, ty = tid >> 4;
    int n = blockIdx.z;
    int y0 = blockIdx.y * 16, x0 = blockIdx.x * 64;
    for (int i = tid; i < 576; i += 256) {
        int ic = i / 9, t = i - ic * 9;
        sW[i] = w[ic * 9 + (8 - t)];
    }
    float acc[4] = {};
    const float* inb = g_g2 + (size_t)n * 64 * 65536;
    for (int ic0 = 0; ic0 < 64; ic0 += 8) {
        __syncthreads();
        for (int i = tid; i < 8 * 18 * 66; i += 256) {
            int j = i / 1188, rem = i - j * 1188, yy = rem / 66, xx = rem - yy * 66;
            int iy = y0 - 1 + yy, ix = x0 - 1 + xx;
            sIn[i] = (iy >= 0 && iy < 256 && ix >= 0 && ix < 256)
                         ? inb[(size_t)(ic0 + j) * 65536 + (size_t)iy * 256 + ix] : 0.f;
        }
        __syncthreads();
#pragma unroll
        for (int j = 0; j < 8; j++) {
            float wr[9];
#pragma unroll
            for (int t = 0; t < 9; t++) wr[t] = sW[(ic0 + j) * 9 + t];
#pragma unroll
            for (int a = 0; a < 3; a++) {
                const float* rp = &sIn[(j * 18 + ty + a) * 66 + tx * 4];
                float v[6];
#pragma unroll
                for (int c = 0; c < 6; c++) v[c] = rp[c];
#pragma unroll
                for (int bb = 0; bb < 3; bb++)
#pragma unroll
                    for (int q = 0; q < 4; q++) acc[q] += v[q + bb] * wr[a * 3 + bb];
            }
        }
    }
    float bias = b[0];
    int oy = y0 + ty, ox = x0 + tx * 4;
    float* ob = out + (size_t)n * 65536 + (size_t)oy * 256 + ox;
#pragma unroll
    for (int q = 0; q < 4; q++) ob[q] = acc[q] + bias;
}

extern "C" void kernel_launch(void* const* d_in, const int* in_sizes, int n_in,
                              void* d_out, int out_size) {
    const float* x   = (const float*)d_in[0];
    const float* ew1 = (const float*)d_in[1];
    const float* eb1 = (const float*)d_in[2];
    const float* ew2 = (const float*)d_in[3];
    const float* eb2 = (const float*)d_in[4];
    const float* ew3 = (const float*)d_in[5];
    const float* eb3 = (const float*)d_in[6];
    const float* emb = (const float*)d_in[7];
    const float* dw1 = (const float*)d_in[8];
    const float* db1 = (const float*)d_in[9];
    const float* dw2 = (const float*)d_in[10];
    const float* db2 = (const float*)d_in[11];
    const float* dw3 = (const float*)d_in[12];
    const float* db3 = (const float*)d_in[13];
    float* out = (float*)d_out;

    float *pq, *pg1, *pg2;
    cudaGetSymbolAddress((void**)&pq,  g_q);
    cudaGetSymbolAddress((void**)&pg1, g_g1);
    cudaGetSymbolAddress((void**)&pg2, g_g2);

    k_init<<<1, 512>>>();
    k_conv1<<<dim3(128, 32), 128>>>(x, ew1, eb1);
    k_conv2<<<dim3(2, 8, 32), 256>>>(ew2, eb2);
    k_conv3<<<dim3(2, 8, 32), 256>>>(ew3, eb3);
    k_ee<<<1, 512>>>(emb);
    k_vq<<<512, 256>>>(emb);
    k_gather<<<1024, 256>>>(emb);
    k_convT<<<dim3(2, 4, 32 * 16), 256>>>(pq, dw1, db1, pg1, 64, 128, 64, 128);
    k_convT<<<dim3(4, 8, 32 * 8), 256>>>(pg1, dw2, db2, pg2, 128, 64, 128, 256);
    k_convT3<<<dim3(4, 16, 32), 256>>>(dw3, db3, out + 1);
    k_finalize<<<1, 512>>>(out, out_size);
}

// round 3
// speedup vs baseline: 1.1427x; 1.1427x over previous
#include <cuda_runtime.h>
#include <math.h>
#include <stdint.h>

typedef unsigned long long u64;

__device__ __forceinline__ u64 pk(float a, float b) {
    u64 r; asm("mov.b64 %0,{%1,%2};" : "=l"(r) : "f"(a), "f"(b)); return r;
}
__device__ __forceinline__ void fma2(u64& d, u64 a, u64 b) {
    asm("fma.rn.f32x2 %0, %1, %2, %0;" : "+l"(d) : "l"(a), "l"(b));
}
__device__ __forceinline__ float2 unpk(u64 x) {
    float2 f; asm("mov.b64 {%0,%1},%2;" : "=f"(f.x), "=f"(f.y) : "l"(x)); return f;
}

// ---------------- scratch ----------------
__device__ float g_h1[67108864];   // [32,128,128,128]
__device__ float g_h2[8388608];    // [32,64,64,64]
__device__ float g_z [8388608];    // NHWC [32,64,64][64]
__device__ float g_q [8388608];    // NCHW [32,64,64,64]
__device__ float g_g1[67108864];   // [32,128,128,128]
__device__ float g_g2[134217728];  // [32,64,256,256]
__device__ int    g_idx[131072];
__device__ float  g_ee[512];
__device__ float  g_counts[512];
__device__ double g_loss_sum;

__global__ void k_init() {
    int t = threadIdx.x;
    if (t < 512) g_counts[t] = 0.f;
    if (t == 0) g_loss_sum = 0.0;
}

// conv1: x[32,1,256,256] -> h1[32,128,128,128], 4x4 s2 p1, relu
__global__ void __launch_bounds__(128) k_conv1(const float* __restrict__ x,
                                               const float* __restrict__ w,
                                               const float* __restrict__ b) {
    __shared__ float sW[2048];
    __shared__ float sB[128];
    int ox = threadIdx.x, oy = blockIdx.x, n = blockIdx.y;
    for (int i = threadIdx.x; i < 2048; i += 128) sW[i] = w[i];
    sB[threadIdx.x] = b[threadIdx.x];
    __syncthreads();
    float p[16];
    const float* xb = x + (size_t)n * 65536;
#pragma unroll
    for (int ky = 0; ky < 4; ky++) {
        int iy = oy * 2 - 1 + ky;
#pragma unroll
        for (int kx = 0; kx < 4; kx++) {
            int ix = ox * 2 - 1 + kx;
            p[ky * 4 + kx] = (iy >= 0 && iy < 256 && ix >= 0 && ix < 256) ? xb[iy * 256 + ix] : 0.f;
        }
    }
    u64 p2[8];
#pragma unroll
    for (int u = 0; u < 8; u++) p2[u] = pk(p[2 * u], p[2 * u + 1]);
    float* ob = g_h1 + (size_t)n * 2097152 + (size_t)oy * 128 + ox;
    for (int c = 0; c < 128; c++) {
        const ulonglong2* wp = (const ulonglong2*)&sW[c * 16];
        u64 a2 = 0ull, b2 = 0ull;
#pragma unroll
        for (int u = 0; u < 4; u++) {
            ulonglong2 t = wp[u];
            fma2(a2, p2[2 * u], t.x);
            fma2(b2, p2[2 * u + 1], t.y);
        }
        float2 fa = unpk(a2), fb = unpk(b2);
        ob[(size_t)c * 16384] = fmaxf((fa.x + fa.y) + (fb.x + fb.y) + sB[c], 0.f);
    }
}

// conv2: h1 -> h2[32,64,64,64], 128ic 4x4 s2 p1, relu. tile 32x*8y*64oc
__global__ void __launch_bounds__(256) k_conv2(const float* __restrict__ w,
                                               const float* __restrict__ b) {
    __shared__ float sIn[4 * 18 * 66];
    __shared__ float sW[4096];
    int tid = threadIdx.x;
    int tx = tid & 7, ty = (tid >> 3) & 7, tz = tid >> 6;
    int n = blockIdx.z, oy0 = blockIdx.y * 8, ox0 = blockIdx.x * 32;
    const float* inb = g_h1 + (size_t)n * 2097152;
    u64 acc2[4][8] = {};
    const int IY0 = oy0 * 2 - 1, IX0 = ox0 * 2 - 1;
    for (int ic0 = 0; ic0 < 128; ic0 += 4) {
        __syncthreads();
        for (int i = tid; i < 4 * 18 * 66; i += 256) {
            int j = i / 1188, rem = i - j * 1188, yy = rem / 66, xx = rem - yy * 66;
            int iy = IY0 + yy, ix = IX0 + xx;
            float v = 0.f;
            if (iy >= 0 && iy < 128 && ix >= 0 && ix < 128)
                v = inb[((size_t)(ic0 + j) * 128 + iy) * 128 + ix];
            sIn[i] = v;
        }
        for (int i = tid; i < 4096; i += 256) {
            int j = i >> 10, rem = i & 1023, t = rem >> 6, oc = rem & 63;
            sW[i] = w[((size_t)(oc << 7) + ic0 + j) * 16 + t];
        }
        __syncthreads();
#pragma unroll
        for (int j = 0; j < 4; j++) {
#pragma unroll
            for (int ky = 0; ky < 4; ky++) {
                const float* rp = &sIn[(j * 18 + ty * 2 + ky) * 66 + tx * 8];
                float v[10];
#pragma unroll
                for (int c = 0; c < 10; c++) v[c] = rp[c];
#pragma unroll
                for (int kx = 0; kx < 4; kx++) {
                    u64 vv0 = pk(v[kx], v[kx]);
                    u64 vv1 = pk(v[kx + 2], v[kx + 2]);
                    u64 vv2 = pk(v[kx + 4], v[kx + 4]);
                    u64 vv3 = pk(v[kx + 6], v[kx + 6]);
                    const ulonglong2* wp = (const ulonglong2*)&sW[((j << 4) + (ky << 2) + kx) * 64 + tz * 16];
                    u64 wv[8];
#pragma unroll
                    for (int u = 0; u < 4; u++) {
                        ulonglong2 t = wp[u];
                        wv[2 * u] = t.x; wv[2 * u + 1] = t.y;
                    }
#pragma unroll
                    for (int o = 0; o < 8; o++) {
                        fma2(acc2[0][o], vv0, wv[o]);
                        fma2(acc2[1][o], vv1, wv[o]);
                        fma2(acc2[2][o], vv2, wv[o]);
                        fma2(acc2[3][o], vv3, wv[o]);
                    }
                }
            }
        }
    }
    int oy = oy0 + ty;
#pragma unroll
    for (int o = 0; o < 8; o++) {
        int oce = tz * 16 + 2 * o;
        float be = b[oce], bo = b[oce + 1];
        float2 a0 = unpk(acc2[0][o]), a1 = unpk(acc2[1][o]), a2 = unpk(acc2[2][o]), a3 = unpk(acc2[3][o]);
        float4 re, ro;
        re.x = fmaxf(a0.x + be, 0.f); re.y = fmaxf(a1.x + be, 0.f);
        re.z = fmaxf(a2.x + be, 0.f); re.w = fmaxf(a3.x + be, 0.f);
        ro.x = fmaxf(a0.y + bo, 0.f); ro.y = fmaxf(a1.y + bo, 0.f);
        ro.z = fmaxf(a2.y + bo, 0.f); ro.w = fmaxf(a3.y + bo, 0.f);
        *(float4*)&g_h2[(((size_t)n * 64 + oce) * 64 + oy) * 64 + ox0 + tx * 4] = re;
        *(float4*)&g_h2[(((size_t)n * 64 + oce + 1) * 64 + oy) * 64 + ox0 + tx * 4] = ro;
    }
}

// conv3: h2 -> z NHWC, 64ic 3x3 s1 p1
__global__ void __launch_bounds__(256) k_conv3(const float* __restrict__ w,
                                               const float* __restrict__ b) {
    __shared__ float sIn[8 * 10 * 34];
    __shared__ float sW[8 * 9 * 64];
    int tid = threadIdx.x;
    int tx = tid & 7, ty = (tid >> 3) & 7, tz = tid >> 6;
    int n = blockIdx.z, oy0 = blockIdx.y * 8, ox0 = blockIdx.x * 32;
    const float* inb = g_h2 + (size_t)n * 262144;
    u64 acc2[4][8] = {};
    for (int ic0 = 0; ic0 < 64; ic0 += 8) {
        __syncthreads();
        for (int i = tid; i < 8 * 10 * 34; i += 256) {
            int j = i / 340, rem = i - j * 340, yy = rem / 34, xx = rem - yy * 34;
            int iy = oy0 - 1 + yy, ix = ox0 - 1 + xx;
            float v = 0.f;
            if (iy >= 0 && iy < 64 && ix >= 0 && ix < 64)
                v = inb[((size_t)(ic0 + j) * 64 + iy) * 64 + ix];
            sIn[i] = v;
        }
        for (int i = tid; i < 8 * 9 * 64; i += 256) {
            int j = i / 576, rem = i - j * 576, t = rem >> 6, oc = rem & 63;
            sW[i] = w[((size_t)oc * 64 + ic0 + j) * 9 + t];
        }
        __syncthreads();
#pragma unroll
        for (int j = 0; j < 8; j++) {
#pragma unroll
            for (int ky = 0; ky < 3; ky++) {
                const float* rp = &sIn[(j * 10 + ty + ky) * 34 + tx * 4];
                u64 vv[6];
#pragma unroll
                for (int c = 0; c < 6; c++) { float t = rp[c]; vv[c] = pk(t, t); }
#pragma unroll
                for (int kx = 0; kx < 3; kx++) {
                    const ulonglong2* wp = (const ulonglong2*)&sW[(j * 9 + ky * 3 + kx) * 64 + tz * 16];
                    u64 wv[8];
#pragma unroll
                    for (int u = 0; u < 4; u++) {
                        ulonglong2 t = wp[u];
                        wv[2 * u] = t.x; wv[2 * u + 1] = t.y;
                    }
#pragma unroll
                    for (int q = 0; q < 4; q++)
#pragma unroll
                        for (int o = 0; o < 8; o++) fma2(acc2[q][o], vv[q + kx], wv[o]);
                }
            }
        }
    }
    int oy = oy0 + ty;
    float bb[16];
#pragma unroll
    for (int i = 0; i < 16; i++) bb[i] = b[tz * 16 + i];
#pragma unroll
    for (int q = 0; q < 4; q++) {
        int ox = ox0 + tx * 4 + q;
        float* zp = g_z + (((size_t)n * 64 + oy) * 64 + ox) * 64 + tz * 16;
#pragma unroll
        for (int o = 0; o < 8; o++) {
            float2 e = unpk(acc2[q][o]);
            float2 r; r.x = e.x + bb[2 * o]; r.y = e.y + bb[2 * o + 1];
            ((float2*)zp)[o] = r;
        }
    }
}

__global__ void k_ee(const float* __restrict__ emb) {
    int k = threadIdx.x;
    float s = 0.f;
    for (int d = 0; d < 64; d++) { float e = emb[d * 512 + k]; s += e * e; }
    g_ee[k] = s;
}

// VQ argmin
__global__ void __launch_bounds__(256) k_vq(const float* __restrict__ emb) {
    __shared__ float sE[64 * 68];
    __shared__ float sEE[64];
    int tid = threadIdx.x;
    int row = blockIdx.x * 256 + tid;
    u64 zr2[32];
    const float4* zp = (const float4*)(g_z + (size_t)row * 64);
#pragma unroll
    for (int j = 0; j < 16; j++) {
        float4 t = zp[j];
        zr2[2 * j]     = pk(t.x, t.y);
        zr2[2 * j + 1] = pk(t.z, t.w);
    }
    float best = 3.4e38f;
    int bi = 0;
    for (int kc = 0; kc < 512; kc += 64) {
        __syncthreads();
        for (int i = tid; i < 4096; i += 256) {
            int d = i >> 6, k = i & 63;
            sE[k * 68 + d] = emb[d * 512 + kc + k];
        }
        if (tid < 64) sEE[tid] = g_ee[kc + tid];
        __syncthreads();
        for (int k = 0; k < 64; k++) {
            const ulonglong2* ep = (const ulonglong2*)&sE[k * 68];
            u64 sa = 0ull, sb = 0ull;
#pragma unroll
            for (int jj = 0; jj < 16; jj++) {
                ulonglong2 e = ep[jj];
                fma2(sa, zr2[2 * jj], e.x);
                fma2(sb, zr2[2 * jj + 1], e.y);
            }
            float2 fa = unpk(sa), fb = unpk(sb);
            float dd = sEE[k] - 2.f * ((fa.x + fa.y) + (fb.x + fb.y));
            if (dd < best) { best = dd; bi = kc + k; }
        }
    }
    g_idx[row] = bi;
    atomicAdd(&g_counts[bi], 1.f);
}

// gather codes + loss + NCHW transpose (128 rows/block)
__global__ void __launch_bounds__(256) k_gather(const float* __restrict__ emb) {
    __shared__ float sQ[8192];
    __shared__ float sRed[256];
    int tid = threadIdx.x;
    int r0 = blockIdx.x * 128;
    int rl = tid & 127, half = tid >> 7;
    int r = r0 + rl;
    int id = g_idx[r];
    const float4* z4 = (const float4*)(g_z + (size_t)r * 64 + half * 32);
    float ls = 0.f;
#pragma unroll
    for (int jj = 0; jj < 8; jj++) {
        float4 zv = z4[jj];
        int d = half * 32 + jj * 4;
        float e0 = emb[(d+0)*512 + id];
        float e1 = emb[(d+1)*512 + id];
        float e2 = emb[(d+2)*512 + id];
        float e3 = emb[(d+3)*512 + id];
        float d0=e0-zv.x, d1=e1-zv.y, d2=e2-zv.z, d3=e3-zv.w;
        ls += d0*d0 + d1*d1 + d2*d2 + d3*d3;
        sQ[(d+0)*128 + rl] = e0;
        sQ[(d+1)*128 + rl] = e1;
        sQ[(d+2)*128 + rl] = e2;
        sQ[(d+3)*128 + rl] = e3;
    }
    __syncthreads();
    int n = r0 >> 12;
    int y0x = r0 & 4095;
    float* qb = g_q + ((size_t)n << 18) + y0x;
    for (int i = tid; i < 8192; i += 256) {
        int d = i >> 7, rl2 = i & 127;
        qb[(size_t)d * 4096 + rl2] = sQ[i];
    }
    sRed[tid] = ls;
    __syncthreads();
    for (int s = 128; s > 0; s >>= 1) {
        if (tid < s) sRed[tid] += sRed[tid + s];
        __syncthreads();
    }
    if (tid == 0) atomicAdd(&g_loss_sum, (double)sRed[0]);
}

__global__ void k_finalize(float* __restrict__ out, int out_size) {
    __shared__ float red[512];
    int t = threadIdx.x;
    float c = g_counts[t];
    float p = c * (1.f / 131072.f);
    red[t] = p * logf(p + 1e-10f);
    __syncthreads();
    for (int s = 256; s > 0; s >>= 1) {
        if (t < s) red[t] += red[t + s];
        __syncthreads();
    }
    if (t == 0) {
        out[out_size - 1] = expf(-red[0]);
        out[0] = (float)(g_loss_sum * (1.25 / 8388608.0));
    }
}

// transposed conv 3x3 s2 p1 op1, relu
__global__ void __launch_bounds__(256) k_convT(const float* __restrict__ in,
                                               const float* __restrict__ w,
                                               const float* __restrict__ b,
                                               float* __restrict__ out,
                                               int IC, int OC, int INS, int OUTS) {
    __shared__ float sIn[8 * 17 * 33];
    __shared__ float sW[576];
    int tid = threadIdx.x;
    int tx = tid & 15, ty = tid >> 4;
    int ocChunks = OC >> 3;
    int z = blockIdx.z;
    int oc0 = (z % ocChunks) * 8;
    int n = z / ocChunks;
    int ux0 = blockIdx.x * 32, uy0 = blockIdx.y * 16;
    const float* inb = in + (size_t)n * IC * INS * INS;
    u64 acc2[2][4][4] = {};
    for (int ic0 = 0; ic0 < IC; ic0 += 8) {
        __syncthreads();
        for (int i = tid; i < 8 * 17 * 33; i += 256) {
            int j = i / 561, rem = i - j * 561, yy = rem / 33, xx = rem - yy * 33;
            int iy = uy0 + yy, ix = ux0 + xx;
            sIn[i] = (iy < INS && ix < INS) ? inb[((size_t)(ic0 + j) * INS + iy) * INS + ix] : 0.f;
        }
        for (int i = tid; i < 576; i += 256) {
            int j = i / 72, rem = i - j * 72, tap = rem >> 3, o = rem & 7;
            sW[i] = w[((size_t)(ic0 + j) * OC + oc0 + o) * 9 + tap];
        }
        __syncthreads();
#pragma unroll
        for (int j = 0; j < 8; j++) {
            float v[2][3];
#pragma unroll
            for (int rr = 0; rr < 2; rr++)
#pragma unroll
                for (int cc = 0; cc < 3; cc++)
                    v[rr][cc] = sIn[(j * 17 + ty + rr) * 33 + 2 * tx + cc];
#pragma unroll
            for (int ky = 0; ky < 3; ky++) {
                int vr = (ky == 0) ? 1 : 0;
                int dy = (ky == 1) ? 0 : 1;
#pragma unroll
                for (int kx = 0; kx < 3; kx++) {
                    const ulonglong2* wp = (const ulonglong2*)&sW[(j * 9 + ky * 3 + kx) * 8];
                    ulonglong2 t0 = wp[0], t1 = wp[1];
                    u64 wv[4] = {t0.x, t0.y, t1.x, t1.y};
                    int c0, dA, c1, dB;
                    if (kx == 0)      { c0 = 1; dA = 1; c1 = 2; dB = 3; }
                    else if (kx == 1) { c0 = 0; dA = 0; c1 = 1; dB = 2; }
                    else              { c0 = 0; dA = 1; c1 = 1; dB = 3; }
                    float va = v[vr][c0], vb = v[vr][c1];
                    u64 pva = pk(va, va), pvb = pk(vb, vb);
#pragma unroll
                    for (int op = 0; op < 4; op++) {
                        fma2(acc2[dy][dA][op], pva, wv[op]);
                        fma2(acc2[dy][dB][op], pvb, wv[op]);
                    }
                }
            }
        }
    }
    int uy = uy0 + ty;
    int oxb = 2 * ux0 + 4 * tx;
#pragma unroll
    for (int op = 0; op < 4; op++) {
        int oce = oc0 + 2 * op;
        float be = b[oce], bo = b[oce + 1];
#pragma unroll
        for (int dy = 0; dy < 2; dy++) {
            int oy = 2 * uy + dy;
            float2 s0 = unpk(acc2[dy][0][op]), s1 = unpk(acc2[dy][1][op]);
            float2 s2 = unpk(acc2[dy][2][op]), s3 = unpk(acc2[dy][3][op]);
            float4 re, ro;
            re.x = fmaxf(s0.x + be, 0.f); re.y = fmaxf(s1.x + be, 0.f);
            re.z = fmaxf(s2.x + be, 0.f); re.w = fmaxf(s3.x + be, 0.f);
            ro.x = fmaxf(s0.y + bo, 0.f); ro.y = fmaxf(s1.y + bo, 0.f);
            ro.z = fmaxf(s2.y + bo, 0.f); ro.w = fmaxf(s3.y + bo, 0.f);
            *(float4*)&out[(((size_t)n * OC + oce) * OUTS + oy) * OUTS + oxb] = re;
            *(float4*)&out[(((size_t)n * OC + oce + 1) * OUTS + oy) * OUTS + oxb] = ro;
        }
    }
}

// convT3: g2 -> recon[32,1,256,256]: conv with flipped kernel, pad1
__global__ void __launch_bounds__(256) k_convT3(const float* __restrict__ w,
                                                const float* __restrict__ b,
                                                float* __restrict__ out) {
    __shared__ float sIn[8 * 18 * 66];
    __shared__ float sW[576];
    int tid = threadIdx.x;
    int tx = tid & 15, ty = tid >> 4;
    int n = blockIdx.z;
    int y0 = blockIdx.y * 16, x0 = blockIdx.x * 64;
    for (int i = tid; i < 576; i += 256) {
        int ic = i / 9, t = i - ic * 9;
        sW[i] = w[ic * 9 + (8 - t)];
    }
    u64 acc2[2] = {};
    const float* inb = g_g2 + (size_t)n * 64 * 65536;
    for (int ic0 = 0; ic0 < 64; ic0 += 8) {
        __syncthreads();
        for (int i = tid; i < 8 * 18 * 66; i += 256) {
            int j = i / 1188, rem = i - j * 1188, yy = rem / 66, xx = rem - yy * 66;
            int iy = y0 - 1 + yy, ix = x0 - 1 + xx;
            sIn[i] = (iy >= 0 && iy < 256 && ix >= 0 && ix < 256)
                         ? inb[(size_t)(ic0 + j) * 65536 + (size_t)iy * 256 + ix] : 0.f;
        }
        __syncthreads();
#pragma unroll
        for (int j = 0; j < 8; j++) {
            u64 wr2[9];
#pragma unroll
            for (int t = 0; t < 9; t++) { float t0 = sW[(ic0 + j) * 9 + t]; wr2[t] = pk(t0, t0); }
#pragma unroll
            for (int a = 0; a < 3; a++) {
                const float* rp = &sIn[(j * 18 + ty + a) * 66 + tx * 4];
                float v[6];
#pragma unroll
                for (int c = 0; c < 6; c++) v[c] = rp[c];
                u64 pv[5];
#pragma unroll
                for (int c = 0; c < 5; c++) pv[c] = pk(v[c], v[c + 1]);
#pragma unroll
                for (int bb = 0; bb < 3; bb++) {
                    fma2(acc2[0], pv[bb], wr2[a * 3 + bb]);
                    fma2(acc2[1], pv[bb + 2], wr2[a * 3 + bb]);
                }
            }
        }
    }
    float bias = b[0];
    int oy = y0 + ty, ox = x0 + tx * 4;
    float* ob = out + (size_t)n * 65536 + (size_t)oy * 256 + ox;
    float2 f0 = unpk(acc2[0]), f1 = unpk(acc2[1]);
    ob[0] = f0.x + bias; ob[1] = f0.y + bias;
    ob[2] = f1.x + bias; ob[3] = f1.y + bias;
}

extern "C" void kernel_launch(void* const* d_in, const int* in_sizes, int n_in,
                              void* d_out, int out_size) {
    const float* x   = (const float*)d_in[0];
    const float* ew1 = (const float*)d_in[1];
    const float* eb1 = (const float*)d_in[2];
    const float* ew2 = (const float*)d_in[3];
    const float* eb2 = (const float*)d_in[4];
    const float* ew3 = (const float*)d_in[5];
    const float* eb3 = (const float*)d_in[6];
    const float* emb = (const float*)d_in[7];
    const float* dw1 = (const float*)d_in[8];
    const float* db1 = (const float*)d_in[9];
    const float* dw2 = (const float*)d_in[10];
    const float* db2 = (const float*)d_in[11];
    const float* dw3 = (const float*)d_in[12];
    const float* db3 = (const float*)d_in[13];
    float* out = (float*)d_out;

    float *pq, *pg1, *pg2;
    cudaGetSymbolAddress((void**)&pq,  g_q);
    cudaGetSymbolAddress((void**)&pg1, g_g1);
    cudaGetSymbolAddress((void**)&pg2, g_g2);

    k_init<<<1, 512>>>();
    k_conv1<<<dim3(128, 32), 128>>>(x, ew1, eb1);
    k_conv2<<<dim3(2, 8, 32), 256>>>(ew2, eb2);
    k_conv3<<<dim3(2, 8, 32), 256>>>(ew3, eb3);
    k_ee<<<1, 512>>>(emb);
    k_vq<<<512, 256>>>(emb);
    k_gather<<<1024, 256>>>(emb);
    k_convT<<<dim3(2, 4, 32 * 16), 256>>>(pq, dw1, db1, pg1, 64, 128, 64, 128);
    k_convT<<<dim3(4, 8, 32 * 8), 256>>>(pg1, dw2, db2, pg2, 128, 64, 128, 256);
    k_convT3<<<dim3(4, 16, 32), 256>>>(dw3, db3, out + 1);
    k_finalize<<<1, 512>>>(out, out_size);
}

// round 4
// speedup vs baseline: 1.2285x; 1.0751x over previous
#include <cuda_runtime.h>
#include <math.h>
#include <stdint.h>

typedef unsigned long long u64;

__device__ __forceinline__ u64 pk(float a, float b) {
    u64 r; asm("mov.b64 %0,{%1,%2};" : "=l"(r) : "f"(a), "f"(b)); return r;
}
__device__ __forceinline__ void fma2(u64& d, u64 a, u64 b) {
    asm("fma.rn.f32x2 %0, %1, %2, %0;" : "+l"(d) : "l"(a), "l"(b));
}
__device__ __forceinline__ float2 unpk(u64 x) {
    float2 f; asm("mov.b64 {%0,%1},%2;" : "=f"(f.x), "=f"(f.y) : "l"(x)); return f;
}
__device__ __forceinline__ uint32_t saddr(const void* p) {
    uint32_t a;
    asm("{.reg .u64 t; cvta.to.shared.u64 t,%1; cvt.u32.u64 %0,t;}" : "=r"(a) : "l"(p));
    return a;
}
__device__ __forceinline__ void cp4(uint32_t dst, const void* src, bool pred) {
    asm volatile("cp.async.ca.shared.global [%0], [%1], 4, %2;"
                 :: "r"(dst), "l"(src), "r"(pred ? 4u : 0u));
}
__device__ __forceinline__ void cp_commit() { asm volatile("cp.async.commit_group;"); }
__device__ __forceinline__ void cp_wait1()  { asm volatile("cp.async.wait_group 1;"); }

// ---------------- scratch ----------------
__device__ float g_h1[67108864];   // [32,128,128,128]
__device__ float g_h2[8388608];    // [32,64,64,64]
__device__ float g_z [8388608];    // NHWC [32,64,64][64]
__device__ float g_q [8388608];    // NCHW [32,64,64,64]
__device__ float g_g1[67108864];   // [32,128,128,128]
__device__ float g_g2[134217728];  // [32,64,256,256]
__device__ int    g_idx[131072];
__device__ float  g_ee[512];
__device__ float  g_counts[512];
__device__ double g_loss_sum;

__global__ void k_init() {
    int t = threadIdx.x;
    if (t < 512) g_counts[t] = 0.f;
    if (t == 0) g_loss_sum = 0.0;
}

// conv1: x[32,1,256,256] -> h1[32,128,128,128], 4x4 s2 p1, relu
__global__ void __launch_bounds__(128) k_conv1(const float* __restrict__ x,
                                               const float* __restrict__ w,
                                               const float* __restrict__ b) {
    __shared__ float sW[2048];
    __shared__ float sB[128];
    int ox = threadIdx.x, oy = blockIdx.x, n = blockIdx.y;
    for (int i = threadIdx.x; i < 2048; i += 128) sW[i] = w[i];
    sB[threadIdx.x] = b[threadIdx.x];
    __syncthreads();
    float p[16];
    const float* xb = x + (size_t)n * 65536;
#pragma unroll
    for (int ky = 0; ky < 4; ky++) {
        int iy = oy * 2 - 1 + ky;
#pragma unroll
        for (int kx = 0; kx < 4; kx++) {
            int ix = ox * 2 - 1 + kx;
            p[ky * 4 + kx] = (iy >= 0 && iy < 256 && ix >= 0 && ix < 256) ? xb[iy * 256 + ix] : 0.f;
        }
    }
    u64 p2[8];
#pragma unroll
    for (int u = 0; u < 8; u++) p2[u] = pk(p[2 * u], p[2 * u + 1]);
    float* ob = g_h1 + (size_t)n * 2097152 + (size_t)oy * 128 + ox;
    for (int c = 0; c < 128; c++) {
        const ulonglong2* wp = (const ulonglong2*)&sW[c * 16];
        u64 a2 = 0ull, b2 = 0ull;
#pragma unroll
        for (int u = 0; u < 4; u++) {
            ulonglong2 t = wp[u];
            fma2(a2, p2[2 * u], t.x);
            fma2(b2, p2[2 * u + 1], t.y);
        }
        float2 fa = unpk(a2), fb = unpk(b2);
        ob[(size_t)c * 16384] = fmaxf((fa.x + fa.y) + (fb.x + fb.y) + sB[c], 0.f);
    }
}

// conv2: h1 -> h2[32,64,64,64], 128ic 4x4 s2 p1, relu. tile 32x*8y*64oc. cp.async 2-stage.
__global__ void __launch_bounds__(256) k_conv2(const float* __restrict__ w,
                                               const float* __restrict__ b) {
    extern __shared__ float sm2[];
    float* sInD = sm2;              // 2 x 4752
    float* sWD  = sm2 + 2 * 4752;   // 2 x 4096
    int tid = threadIdx.x;
    int tx = tid & 7, ty = (tid >> 3) & 7, tz = tid >> 6;
    int n = blockIdx.z, oy0 = blockIdx.y * 8, ox0 = blockIdx.x * 32;
    const float* inb = g_h1 + (size_t)n * 2097152;
    u64 acc2[4][8] = {};
    const int IY0 = oy0 * 2 - 1, IX0 = ox0 * 2 - 1;

    auto fill = [&](int ic0, int buf) {
        float* dI = sInD + buf * 4752;
        for (int i = tid; i < 4752; i += 256) {
            int j = i / 1188, rem = i - j * 1188, yy = rem / 66, xx = rem - yy * 66;
            int iy = IY0 + yy, ix = IX0 + xx;
            bool pr = (iy >= 0 && iy < 128 && ix >= 0 && ix < 128);
            const float* sp = pr ? &inb[((size_t)(ic0 + j) * 128 + iy) * 128 + ix] : inb;
            cp4(saddr(dI + i), sp, pr);
        }
        float* dW = sWD + buf * 4096;
        for (int i = tid; i < 4096; i += 256) {
            int j = i >> 10, rem = i & 1023, t = rem >> 6, oc = rem & 63;
            cp4(saddr(dW + i), &w[((size_t)(oc << 7) + ic0 + j) * 16 + t], true);
        }
    };

    fill(0, 0);
    cp_commit();
    for (int c = 0; c < 32; c++) {
        int buf = c & 1;
        if (c + 1 < 32) fill((c + 1) * 4, (c + 1) & 1);
        cp_commit();
        cp_wait1();
        __syncthreads();
        const float* pI = sInD + buf * 4752;
        const float* pW = sWD + buf * 4096;
#pragma unroll
        for (int j = 0; j < 4; j++) {
#pragma unroll
            for (int ky = 0; ky < 4; ky++) {
                const float* rp = &pI[(j * 18 + ty * 2 + ky) * 66 + tx * 8];
                float v[10];
#pragma unroll
                for (int cc = 0; cc < 10; cc++) v[cc] = rp[cc];
#pragma unroll
                for (int kx = 0; kx < 4; kx++) {
                    u64 vv0 = pk(v[kx], v[kx]);
                    u64 vv1 = pk(v[kx + 2], v[kx + 2]);
                    u64 vv2 = pk(v[kx + 4], v[kx + 4]);
                    u64 vv3 = pk(v[kx + 6], v[kx + 6]);
                    const ulonglong2* wp = (const ulonglong2*)&pW[((j << 4) + (ky << 2) + kx) * 64 + tz * 16];
                    u64 wv[8];
#pragma unroll
                    for (int u = 0; u < 4; u++) {
                        ulonglong2 t = wp[u];
                        wv[2 * u] = t.x; wv[2 * u + 1] = t.y;
                    }
#pragma unroll
                    for (int o = 0; o < 8; o++) {
                        fma2(acc2[0][o], vv0, wv[o]);
                        fma2(acc2[1][o], vv1, wv[o]);
                        fma2(acc2[2][o], vv2, wv[o]);
                        fma2(acc2[3][o], vv3, wv[o]);
                    }
                }
            }
        }
        __syncthreads();
    }
    int oy = oy0 + ty;
#pragma unroll
    for (int o = 0; o < 8; o++) {
        int oce = tz * 16 + 2 * o;
        float be = b[oce], bo = b[oce + 1];
        float2 a0 = unpk(acc2[0][o]), a1 = unpk(acc2[1][o]), a2 = unpk(acc2[2][o]), a3 = unpk(acc2[3][o]);
        float4 re, ro;
        re.x = fmaxf(a0.x + be, 0.f); re.y = fmaxf(a1.x + be, 0.f);
        re.z = fmaxf(a2.x + be, 0.f); re.w = fmaxf(a3.x + be, 0.f);
        ro.x = fmaxf(a0.y + bo, 0.f); ro.y = fmaxf(a1.y + bo, 0.f);
        ro.z = fmaxf(a2.y + bo, 0.f); ro.w = fmaxf(a3.y + bo, 0.f);
        *(float4*)&g_h2[(((size_t)n * 64 + oce) * 64 + oy) * 64 + ox0 + tx * 4] = re;
        *(float4*)&g_h2[(((size_t)n * 64 + oce + 1) * 64 + oy) * 64 + ox0 + tx * 4] = ro;
    }
}

// conv3: h2 -> z NHWC, 64ic 3x3 s1 p1. cp.async 2-stage.
__global__ void __launch_bounds__(256) k_conv3(const float* __restrict__ w,
                                               const float* __restrict__ b) {
    extern __shared__ float sm3[];
    float* sInD = sm3;              // 2 x 2720
    float* sWD  = sm3 + 2 * 2720;   // 2 x 4608
    int tid = threadIdx.x;
    int tx = tid & 7, ty = (tid >> 3) & 7, tz = tid >> 6;
    int n = blockIdx.z, oy0 = blockIdx.y * 8, ox0 = blockIdx.x * 32;
    const float* inb = g_h2 + (size_t)n * 262144;
    u64 acc2[4][8] = {};

    auto fill = [&](int ic0, int buf) {
        float* dI = sInD + buf * 2720;
        for (int i = tid; i < 2720; i += 256) {
            int j = i / 340, rem = i - j * 340, yy = rem / 34, xx = rem - yy * 34;
            int iy = oy0 - 1 + yy, ix = ox0 - 1 + xx;
            bool pr = (iy >= 0 && iy < 64 && ix >= 0 && ix < 64);
            const float* sp = pr ? &inb[((size_t)(ic0 + j) * 64 + iy) * 64 + ix] : inb;
            cp4(saddr(dI + i), sp, pr);
        }
        float* dW = sWD + buf * 4608;
        for (int i = tid; i < 4608; i += 256) {
            int j = i / 576, rem = i - j * 576, t = rem >> 6, oc = rem & 63;
            cp4(saddr(dW + i), &w[((size_t)oc * 64 + ic0 + j) * 9 + t], true);
        }
    };

    fill(0, 0);
    cp_commit();
    for (int c = 0; c < 8; c++) {
        int buf = c & 1;
        if (c + 1 < 8) fill((c + 1) * 8, (c + 1) & 1);
        cp_commit();
        cp_wait1();
        __syncthreads();
        const float* pI = sInD + buf * 2720;
        const float* pW = sWD + buf * 4608;
#pragma unroll
        for (int j = 0; j < 8; j++) {
#pragma unroll
            for (int ky = 0; ky < 3; ky++) {
                const float* rp = &pI[(j * 10 + ty + ky) * 34 + tx * 4];
                u64 vv[6];
#pragma unroll
                for (int cc = 0; cc < 6; cc++) { float t = rp[cc]; vv[cc] = pk(t, t); }
#pragma unroll
                for (int kx = 0; kx < 3; kx++) {
                    const ulonglong2* wp = (const ulonglong2*)&pW[(j * 9 + ky * 3 + kx) * 64 + tz * 16];
                    u64 wv[8];
#pragma unroll
                    for (int u = 0; u < 4; u++) {
                        ulonglong2 t = wp[u];
                        wv[2 * u] = t.x; wv[2 * u + 1] = t.y;
                    }
#pragma unroll
                    for (int q = 0; q < 4; q++)
#pragma unroll
                        for (int o = 0; o < 8; o++) fma2(acc2[q][o], vv[q + kx], wv[o]);
                }
            }
        }
        __syncthreads();
    }
    int oy = oy0 + ty;
    float bb[16];
#pragma unroll
    for (int i = 0; i < 16; i++) bb[i] = b[tz * 16 + i];
#pragma unroll
    for (int q = 0; q < 4; q++) {
        int ox = ox0 + tx * 4 + q;
        float* zp = g_z + (((size_t)n * 64 + oy) * 64 + ox) * 64 + tz * 16;
#pragma unroll
        for (int o = 0; o < 8; o++) {
            float2 e = unpk(acc2[q][o]);
            float2 r; r.x = e.x + bb[2 * o]; r.y = e.y + bb[2 * o + 1];
            ((float2*)zp)[o] = r;
        }
    }
}

__global__ void k_ee(const float* __restrict__ emb) {
    int k = threadIdx.x;
    float s = 0.f;
    for (int d = 0; d < 64; d++) { float e = emb[d * 512 + k]; s += e * e; }
    g_ee[k] = s;
}

// VQ argmin
__global__ void __launch_bounds__(256) k_vq(const float* __restrict__ emb) {
    __shared__ float sE[64 * 68];
    __shared__ float sEE[64];
    int tid = threadIdx.x;
    int row = blockIdx.x * 256 + tid;
    u64 zr2[32];
    const float4* zp = (const float4*)(g_z + (size_t)row * 64);
#pragma unroll
    for (int j = 0; j < 16; j++) {
        float4 t = zp[j];
        zr2[2 * j]     = pk(t.x, t.y);
        zr2[2 * j + 1] = pk(t.z, t.w);
    }
    float best = 3.4e38f;
    int bi = 0;
    for (int kc = 0; kc < 512; kc += 64) {
        __syncthreads();
        for (int i = tid; i < 4096; i += 256) {
            int d = i >> 6, k = i & 63;
            sE[k * 68 + d] = emb[d * 512 + kc + k];
        }
        if (tid < 64) sEE[tid] = g_ee[kc + tid];
        __syncthreads();
        for (int k = 0; k < 64; k++) {
            const ulonglong2* ep = (const ulonglong2*)&sE[k * 68];
            u64 sa = 0ull, sb = 0ull;
#pragma unroll
            for (int jj = 0; jj < 16; jj++) {
                ulonglong2 e = ep[jj];
                fma2(sa, zr2[2 * jj], e.x);
                fma2(sb, zr2[2 * jj + 1], e.y);
            }
            float2 fa = unpk(sa), fb = unpk(sb);
            float dd = sEE[k] - 2.f * ((fa.x + fa.y) + (fb.x + fb.y));
            if (dd < best) { best = dd; bi = kc + k; }
        }
    }
    g_idx[row] = bi;
    atomicAdd(&g_counts[bi], 1.f);
}

// gather codes + loss + NCHW transpose (128 rows/block)
__global__ void __launch_bounds__(256) k_gather(const float* __restrict__ emb) {
    __shared__ float sQ[8192];
    __shared__ float sRed[256];
    int tid = threadIdx.x;
    int r0 = blockIdx.x * 128;
    int rl = tid & 127, half = tid >> 7;
    int r = r0 + rl;
    int id = g_idx[r];
    const float4* z4 = (const float4*)(g_z + (size_t)r * 64 + half * 32);
    float ls = 0.f;
#pragma unroll
    for (int jj = 0; jj < 8; jj++) {
        float4 zv = z4[jj];
        int d = half * 32 + jj * 4;
        float e0 = emb[(d+0)*512 + id];
        float e1 = emb[(d+1)*512 + id];
        float e2 = emb[(d+2)*512 + id];
        float e3 = emb[(d+3)*512 + id];
        float d0=e0-zv.x, d1=e1-zv.y, d2=e2-zv.z, d3=e3-zv.w;
        ls += d0*d0 + d1*d1 + d2*d2 + d3*d3;
        sQ[(d+0)*128 + rl] = e0;
        sQ[(d+1)*128 + rl] = e1;
        sQ[(d+2)*128 + rl] = e2;
        sQ[(d+3)*128 + rl] = e3;
    }
    __syncthreads();
    int n = r0 >> 12;
    int y0x = r0 & 4095;
    float* qb = g_q + ((size_t)n << 18) + y0x;
    for (int i = tid; i < 8192; i += 256) {
        int d = i >> 7, rl2 = i & 127;
        qb[(size_t)d * 4096 + rl2] = sQ[i];
    }
    sRed[tid] = ls;
    __syncthreads();
    for (int s = 128; s > 0; s >>= 1) {
        if (tid < s) sRed[tid] += sRed[tid + s];
        __syncthreads();
    }
    if (tid == 0) atomicAdd(&g_loss_sum, (double)sRed[0]);
}

__global__ void k_finalize(float* __restrict__ out, int out_size) {
    __shared__ float red[512];
    int t = threadIdx.x;
    float c = g_counts[t];
    float p = c * (1.f / 131072.f);
    red[t] = p * logf(p + 1e-10f);
    __syncthreads();
    for (int s = 256; s > 0; s >>= 1) {
        if (t < s) red[t] += red[t + s];
        __syncthreads();
    }
    if (t == 0) {
        out[out_size - 1] = expf(-red[0]);
        out[0] = (float)(g_loss_sum * (1.25 / 8388608.0));
    }
}

// transposed conv 3x3 s2 p1 op1, relu. cp.async 2-stage (static smem: 40.5KB).
__global__ void __launch_bounds__(256) k_convT(const float* __restrict__ in,
                                               const float* __restrict__ w,
                                               const float* __restrict__ b,
                                               float* __restrict__ out,
                                               int IC, int OC, int INS, int OUTS) {
    __shared__ float sIn[2][4488];   // 8*17*33
    __shared__ float sW[2][576];
    int tid = threadIdx.x;
    int tx = tid & 15, ty = tid >> 4;
    int ocChunks = OC >> 3;
    int z = blockIdx.z;
    int oc0 = (z % ocChunks) * 8;
    int n = z / ocChunks;
    int ux0 = blockIdx.x * 32, uy0 = blockIdx.y * 16;
    const float* inb = in + (size_t)n * IC * INS * INS;
    u64 acc2[2][4][4] = {};
    int K = IC >> 3;

    auto fill = [&](int ic0, int buf) {
        for (int i = tid; i < 4488; i += 256) {
            int j = i / 561, rem = i - j * 561, yy = rem / 33, xx = rem - yy * 33;
            int iy = uy0 + yy, ix = ux0 + xx;
            bool pr = (iy < INS && ix < INS);
            const float* sp = pr ? &inb[((size_t)(ic0 + j) * INS + iy) * INS + ix] : inb;
            cp4(saddr(&sIn[buf][i]), sp, pr);
        }
        for (int i = tid; i < 576; i += 256) {
            int j = i / 72, rem = i - j * 72, tap = rem >> 3, o = rem & 7;
            cp4(saddr(&sW[buf][i]), &w[((size_t)(ic0 + j) * OC + oc0 + o) * 9 + tap], true);
        }
    };

    fill(0, 0);
    cp_commit();
    for (int c = 0; c < K; c++) {
        int buf = c & 1;
        if (c + 1 < K) fill((c + 1) * 8, (c + 1) & 1);
        cp_commit();
        cp_wait1();
        __syncthreads();
#pragma unroll
        for (int j = 0; j < 8; j++) {
            float v[2][3];
#pragma unroll
            for (int rr = 0; rr < 2; rr++)
#pragma unroll
                for (int cc = 0; cc < 3; cc++)
                    v[rr][cc] = sIn[buf][(j * 17 + ty + rr) * 33 + 2 * tx + cc];
#pragma unroll
            for (int ky = 0; ky < 3; ky++) {
                int vr = (ky == 0) ? 1 : 0;
                int dy = (ky == 1) ? 0 : 1;
#pragma unroll
                for (int kx = 0; kx < 3; kx++) {
                    const ulonglong2* wp = (const ulonglong2*)&sW[buf][(j * 9 + ky * 3 + kx) * 8];
                    ulonglong2 t0 = wp[0], t1 = wp[1];
                    u64 wv[4] = {t0.x, t0.y, t1.x, t1.y};
                    int c0, dA, c1, dB;
                    if (kx == 0)      { c0 = 1; dA = 1; c1 = 2; dB = 3; }
                    else if (kx == 1) { c0 = 0; dA = 0; c1 = 1; dB = 2; }
                    else              { c0 = 0; dA = 1; c1 = 1; dB = 3; }
                    float va = v[vr][c0], vb = v[vr][c1];
                    u64 pva = pk(va, va), pvb = pk(vb, vb);
#pragma unroll
                    for (int op = 0; op < 4; op++) {
                        fma2(acc2[dy][dA][op], pva, wv[op]);
                        fma2(acc2[dy][dB][op], pvb, wv[op]);
                    }
                }
            }
        }
        __syncthreads();
    }
    int uy = uy0 + ty;
    int oxb = 2 * ux0 + 4 * tx;
#pragma unroll
    for (int op = 0; op < 4; op++) {
        int oce = oc0 + 2 * op;
        float be = b[oce], bo = b[oce + 1];
#pragma unroll
        for (int dy = 0; dy < 2; dy++) {
            int oy = 2 * uy + dy;
            float2 s0 = unpk(acc2[dy][0][op]), s1 = unpk(acc2[dy][1][op]);
            float2 s2 = unpk(acc2[dy][2][op]), s3 = unpk(acc2[dy][3][op]);
            float4 re, ro;
            re.x = fmaxf(s0.x + be, 0.f); re.y = fmaxf(s1.x + be, 0.f);
            re.z = fmaxf(s2.x + be, 0.f); re.w = fmaxf(s3.x + be, 0.f);
            ro.x = fmaxf(s0.y + bo, 0.f); ro.y = fmaxf(s1.y + bo, 0.f);
            ro.z = fmaxf(s2.y + bo, 0.f); ro.w = fmaxf(s3.y + bo, 0.f);
            *(float4*)&out[(((size_t)n * OC + oce) * OUTS + oy) * OUTS + oxb] = re;
            *(float4*)&out[(((size_t)n * OC + oce + 1) * OUTS + oy) * OUTS + oxb] = ro;
        }
    }
}

// convT3: g2 -> recon[32,1,256,256]: conv with flipped kernel, pad1. cp.async 2-stage.
__global__ void __launch_bounds__(256) k_convT3(const float* __restrict__ w,
                                                const float* __restrict__ b,
                                                float* __restrict__ out) {
    extern __shared__ float smT[];
    float* sInD = smT;               // 2 x 9504 (8*18*66)
    float* sW   = smT + 2 * 9504;    // 576
    int tid = threadIdx.x;
    int tx = tid & 15, ty = tid >> 4;
    int n = blockIdx.z;
    int y0 = blockIdx.y * 16, x0 = blockIdx.x * 64;
    for (int i = tid; i < 576; i += 256) {
        int ic = i / 9, t = i - ic * 9;
        sW[i] = w[ic * 9 + (8 - t)];
    }
    u64 acc2[2] = {};
    const float* inb = g_g2 + (size_t)n * 64 * 65536;

    auto fill = [&](int ic0, int buf) {
        float* dI = sInD + buf * 9504;
        for (int i = tid; i < 9504; i += 256) {
            int j = i / 1188, rem = i - j * 1188, yy = rem / 66, xx = rem - yy * 66;
            int iy = y0 - 1 + yy, ix = x0 - 1 + xx;
            bool pr = (iy >= 0 && iy < 256 && ix >= 0 && ix < 256);
            const float* sp = pr ? &inb[(size_t)(ic0 + j) * 65536 + (size_t)iy * 256 + ix] : inb;
            cp4(saddr(dI + i), sp, pr);
        }
    };

    fill(0, 0);
    cp_commit();
    for (int c = 0; c < 8; c++) {
        int buf = c & 1;
        if (c + 1 < 8) fill((c + 1) * 8, (c + 1) & 1);
        cp_commit();
        cp_wait1();
        __syncthreads();
        const float* pI = sInD + buf * 9504;
        int ic0 = c * 8;
#pragma unroll
        for (int j = 0; j < 8; j++) {
            u64 wr2[9];
#pragma unroll
            for (int t = 0; t < 9; t++) { float t0 = sW[(ic0 + j) * 9 + t]; wr2[t] = pk(t0, t0); }
#pragma unroll
            for (int a = 0; a < 3; a++) {
                const float* rp = &pI[(j * 18 + ty + a) * 66 + tx * 4];
                float v[6];
#pragma unroll
                for (int cc = 0; cc < 6; cc++) v[cc] = rp[cc];
                u64 pv[5];
#pragma unroll
                for (int cc = 0; cc < 5; cc++) pv[cc] = pk(v[cc], v[cc + 1]);
#pragma unroll
                for (int bb = 0; bb < 3; bb++) {
                    fma2(acc2[0], pv[bb], wr2[a * 3 + bb]);
                    fma2(acc2[1], pv[bb + 2], wr2[a * 3 + bb]);
                }
            }
        }
        __syncthreads();
    }
    float bias = b[0];
    int oy = y0 + ty, ox = x0 + tx * 4;
    float* ob = out + (size_t)n * 65536 + (size_t)oy * 256 + ox;
    float2 f0 = unpk(acc2[0]), f1 = unpk(acc2[1]);
    ob[0] = f0.x + bias; ob[1] = f0.y + bias;
    ob[2] = f1.x + bias; ob[3] = f1.y + bias;
}

extern "C" void kernel_launch(void* const* d_in, const int* in_sizes, int n_in,
                              void* d_out, int out_size) {
    const float* x   = (const float*)d_in[0];
    const float* ew1 = (const float*)d_in[1];
    const float* eb1 = (const float*)d_in[2];
    const float* ew2 = (const float*)d_in[3];
    const float* eb2 = (const float*)d_in[4];
    const float* ew3 = (const float*)d_in[5];
    const float* eb3 = (const float*)d_in[6];
    const float* emb = (const float*)d_in[7];
    const float* dw1 = (const float*)d_in[8];
    const float* db1 = (const float*)d_in[9];
    const float* dw2 = (const float*)d_in[10];
    const float* db2 = (const float*)d_in[11];
    const float* dw3 = (const float*)d_in[12];
    const float* db3 = (const float*)d_in[13];
    float* out = (float*)d_out;

    float *pq, *pg1, *pg2;
    cudaGetSymbolAddress((void**)&pq,  g_q);
    cudaGetSymbolAddress((void**)&pg1, g_g1);
    cudaGetSymbolAddress((void**)&pg2, g_g2);

    const int smem2 = (2 * 4752 + 2 * 4096) * 4;   // 70784
    const int smem3 = (2 * 2720 + 2 * 4608) * 4;   // 58624
    const int smemT3 = (2 * 9504 + 576) * 4;       // 78336
    cudaFuncSetAttribute(k_conv2, cudaFuncAttributeMaxDynamicSharedMemorySize, smem2);
    cudaFuncSetAttribute(k_conv3, cudaFuncAttributeMaxDynamicSharedMemorySize, smem3);
    cudaFuncSetAttribute(k_convT3, cudaFuncAttributeMaxDynamicSharedMemorySize, smemT3);

    k_init<<<1, 512>>>();
    k_conv1<<<dim3(128, 32), 128>>>(x, ew1, eb1);
    k_conv2<<<dim3(2, 8, 32), 256, smem2>>>(ew2, eb2);
    k_conv3<<<dim3(2, 8, 32), 256, smem3>>>(ew3, eb3);
    k_ee<<<1, 512>>>(emb);
    k_vq<<<512, 256>>>(emb);
    k_gather<<<1024, 256>>>(emb);
    k_convT<<<dim3(2, 4, 32 * 16), 256>>>(pq, dw1, db1, pg1, 64, 128, 64, 128);
    k_convT<<<dim3(4, 8, 32 * 8), 256>>>(pg1, dw2, db2, pg2, 128, 64, 128, 256);
    k_convT3<<<dim3(4, 16, 32), 256, smemT3>>>(dw3, db3, out + 1);
    k_finalize<<<1, 512>>>(out, out_size);
}